// round 13
// baseline (speedup 1.0000x reference)
#include <cuda_runtime.h>
#include <math.h>
#include <stdint.h>

#define HH 40
#define WW 40
#define CIN 2048
#define NPIX 1600
#define CMID 256
#define NA 5
#define NBOX 8000
#define NWORD 125
#define MAXDET 300

#define NT1D 10
#define NTILE 100            // 10x10 F(4x4) tiles
#define VSTRIDE (NTILE * CIN)
#define KSTRIDE (CIN * CMID)
#define DSTRIDE (128 * CMID)
#define KC3 16
#define KPS 512
#define CHKS (KPS / KC3)     // 32

#define WT_BLOCKS ((CIN * CMID) / 256)   // 2048
#define VT_BLOCKS ((NTILE * CIN) / 256)  // 800
#define HP_BLOCKS 30                     // head-weight transpose (7680 threads)

// ---------------- device scratch (static, no allocation) ----------------
__device__ float g_Vt[36 * VSTRIDE];
__device__ float g_Wt[36 * KSTRIDE];
__device__ float g_D[144 * DSTRIDE];
__device__ float g_x[NPIX * CMID];
__device__ float g_wcT[10 * CMID];   // transposed cls_w [o][k]
__device__ float g_wrT[20 * CMID];   // transposed reg_w [o][k]
__device__ float g_scores[NBOX];
__device__ float g_boxes[NBOX * 4];
__device__ float g_boxsorted[NBOX * 4];
__device__ int g_rank[NBOX];
__device__ unsigned long long g_mask[(size_t)NBOX * NWORD];
__device__ float g_rois[MAXDET * 4];

__device__ __forceinline__ uint32_t smem_u32(const void* p) {
  uint32_t a;
  asm("{ .reg .u64 t; cvta.to.shared.u64 t, %1; cvt.u32.u64 %0, t; }" : "=r"(a) : "l"(p));
  return a;
}
__device__ __forceinline__ void cp16(uint32_t dst, const void* src) {
  asm volatile("cp.async.ca.shared.global [%0], [%1], 16;" ::"r"(dst), "l"(src) : "memory");
}
#define CP_COMMIT() asm volatile("cp.async.commit_group;" ::: "memory")
#define CP_WAIT0() asm volatile("cp.async.wait_group 0;" ::: "memory")

__device__ __forceinline__ unsigned long long score_key(int i) {
  uint32_t u = __float_as_uint(g_scores[i]);
  uint32_t ou = (u & 0x80000000u) ? ~u : (u | 0x80000000u);
  return ((unsigned long long)(~ou) << 13) | (unsigned)i;
}

// ---------------- K0: fused transforms (weights, input, head-weight transpose) ----------------
__device__ __forceinline__ void wt_body(const float* __restrict__ w, int blk) {
  const int idx = blk * 256 + threadIdx.x;
  float g[3][3];
#pragma unroll
  for (int i = 0; i < 3; i++)
#pragma unroll
    for (int j = 0; j < 3; j++) g[i][j] = w[(size_t)(i * 3 + j) * KSTRIDE + idx];
  float T[6][3];
#pragma unroll
  for (int j = 0; j < 3; j++) {
    T[0][j] = 0.25f * g[0][j];
    T[1][j] = -0.16666667f * (g[0][j] + g[1][j] + g[2][j]);
    T[2][j] = 0.16666667f * (-g[0][j] + g[1][j] - g[2][j]);
    T[3][j] = 0.041666668f * g[0][j] + 0.083333336f * g[1][j] + 0.16666667f * g[2][j];
    T[4][j] = 0.041666668f * g[0][j] - 0.083333336f * g[1][j] + 0.16666667f * g[2][j];
    T[5][j] = g[2][j];
  }
#pragma unroll
  for (int i = 0; i < 6; i++) {
    float u[6];
    u[0] = 0.25f * T[i][0];
    u[1] = -0.16666667f * (T[i][0] + T[i][1] + T[i][2]);
    u[2] = 0.16666667f * (-T[i][0] + T[i][1] - T[i][2]);
    u[3] = 0.041666668f * T[i][0] + 0.083333336f * T[i][1] + 0.16666667f * T[i][2];
    u[4] = 0.041666668f * T[i][0] - 0.083333336f * T[i][1] + 0.16666667f * T[i][2];
    u[5] = T[i][2];
#pragma unroll
    for (int j = 0; j < 6; j++)
      g_Wt[(size_t)(i * 6 + j) * KSTRIDE + idx] = u[j];
  }
}

__device__ __forceinline__ void vt_body(const float* __restrict__ feat, int blk) {
  const int idx = blk * 256 + threadIdx.x;
  const int tile = idx >> 11, k = idx & 2047;
  const int ty = tile / NT1D, tx = tile % NT1D;
  const int oy = 4 * ty - 1, ox = 4 * tx - 1;
  float d[6][6];
#pragma unroll
  for (int i = 0; i < 6; i++) {
    const int py = oy + i;
    const bool yok = (py >= 0 && py < HH);
#pragma unroll
    for (int j = 0; j < 6; j++) {
      const int px = ox + j;
      d[i][j] = (yok && px >= 0 && px < WW)
                    ? feat[(size_t)(py * WW + px) * CIN + k] : 0.f;
    }
  }
  float t[6][6];
#pragma unroll
  for (int j = 0; j < 6; j++) {
    t[0][j] = 4.f * d[0][j] - 5.f * d[2][j] + d[4][j];
    t[1][j] = -4.f * d[1][j] - 4.f * d[2][j] + d[3][j] + d[4][j];
    t[2][j] = 4.f * d[1][j] - 4.f * d[2][j] - d[3][j] + d[4][j];
    t[3][j] = -2.f * d[1][j] - d[2][j] + 2.f * d[3][j] + d[4][j];
    t[4][j] = 2.f * d[1][j] - d[2][j] - 2.f * d[3][j] + d[4][j];
    t[5][j] = 4.f * d[1][j] - 5.f * d[3][j] + d[5][j];
  }
  const size_t base = (size_t)tile * CIN + k;
#pragma unroll
  for (int i = 0; i < 6; i++) {
    float v[6];
    v[0] = 4.f * t[i][0] - 5.f * t[i][2] + t[i][4];
    v[1] = -4.f * t[i][1] - 4.f * t[i][2] + t[i][3] + t[i][4];
    v[2] = 4.f * t[i][1] - 4.f * t[i][2] - t[i][3] + t[i][4];
    v[3] = -2.f * t[i][1] - t[i][2] + 2.f * t[i][3] + t[i][4];
    v[4] = 2.f * t[i][1] - t[i][2] - 2.f * t[i][3] + t[i][4];
    v[5] = 4.f * t[i][1] - 5.f * t[i][3] + t[i][5];
#pragma unroll
    for (int j = 0; j < 6; j++)
      g_Vt[(size_t)(i * 6 + j) * VSTRIDE + base] = v[j];
  }
}

__device__ __forceinline__ void hp_body(const float* __restrict__ cls_w,
                                        const float* __restrict__ reg_w, int blk) {
  const int idx = blk * 256 + threadIdx.x;
  if (idx < 10 * CMID) {
    const int o = idx >> 8, k = idx & 255;
    g_wcT[idx] = cls_w[k * 10 + o];
  } else if (idx < 30 * CMID) {
    const int i2 = idx - 10 * CMID;
    const int o = i2 >> 8, k = i2 & 255;
    g_wrT[i2] = reg_w[k * 20 + o];
  }
}

__global__ __launch_bounds__(256) void transform_kernel(const float* __restrict__ w,
                                                        const float* __restrict__ feat,
                                                        const float* __restrict__ cls_w,
                                                        const float* __restrict__ reg_w) {
  const int b = blockIdx.x;
  if (b < WT_BLOCKS) wt_body(w, b);
  else if (b < WT_BLOCKS + VT_BLOCKS) vt_body(feat, b - WT_BLOCKS);
  else hp_body(cls_w, reg_w, b - WT_BLOCKS - VT_BLOCKS);
}

// ---------------- K1: winograd GEMM, 64x128 tile, 8x8/thread ----------------
__global__ __launch_bounds__(128) void wino_gemm_kernel() {
  __shared__ __align__(16) float As[2][KC3][64];
  __shared__ __align__(16) float Bs[2][KC3][128];

  const int mt = blockIdx.x;
  const int nt = blockIdx.y;
  const int z = blockIdx.z;
  const int xi = z >> 2;
  const int ks = z & 3;
  const int tid = threadIdx.x;
  const int warp = tid >> 5;
  const int lane = tid & 31;
  const int rg = lane >> 2;
  const int cg = lane & 3;
  const int am_off = rg * 8;
  const int bn_off = warp * 32 + cg * 8;

  const int am = tid & 63;
  const int akg = (tid >> 6) * 8;
  const int m = mt * 64 + am;
  const bool aval = (m < NTILE);
  const float* arow =
      g_Vt + (size_t)xi * VSTRIDE + (size_t)(aval ? m : 0) * CIN + ks * KPS + akg;

  const int bk = tid >> 3;
  const int bn = (tid & 7) * 16;
  const int n0 = nt * 128;
  const float* bsrc = g_Wt + (size_t)xi * KSTRIDE + (size_t)(ks * KPS + bk) * CMID + n0 + bn;

  float acc[8][8];
#pragma unroll
  for (int i = 0; i < 8; i++)
#pragma unroll
    for (int j = 0; j < 8; j++) acc[i][j] = 0.f;

  {
    float4 ra0 = aval ? *(const float4*)arow : make_float4(0.f, 0.f, 0.f, 0.f);
    float4 ra1 = aval ? *(const float4*)(arow + 4) : make_float4(0.f, 0.f, 0.f, 0.f);
#pragma unroll
    for (int i = 0; i < 4; i++) cp16(smem_u32(&Bs[0][bk][bn + i * 4]), bsrc + i * 4);
    CP_COMMIT();
    As[0][akg + 0][am] = ra0.x;
    As[0][akg + 1][am] = ra0.y;
    As[0][akg + 2][am] = ra0.z;
    As[0][akg + 3][am] = ra0.w;
    As[0][akg + 4][am] = ra1.x;
    As[0][akg + 5][am] = ra1.y;
    As[0][akg + 6][am] = ra1.z;
    As[0][akg + 7][am] = ra1.w;
    CP_WAIT0();
  }
  __syncthreads();

#pragma unroll 1
  for (int c = 0; c < CHKS; c++) {
    const int cur = c & 1;
    const int nxtb = cur ^ 1;
    float4 ra0, ra1;
    const bool more = (c + 1 < CHKS);
    if (more) {
      const int k0 = (c + 1) * KC3;
      ra0 = aval ? *(const float4*)(arow + k0) : make_float4(0.f, 0.f, 0.f, 0.f);
      ra1 = aval ? *(const float4*)(arow + k0 + 4) : make_float4(0.f, 0.f, 0.f, 0.f);
      const float* bs = bsrc + (size_t)k0 * CMID;
#pragma unroll
      for (int i = 0; i < 4; i++) cp16(smem_u32(&Bs[nxtb][bk][bn + i * 4]), bs + i * 4);
      CP_COMMIT();
    }
#pragma unroll
    for (int k = 0; k < KC3; k++) {
      float4 a0 = *(const float4*)&As[cur][k][am_off];
      float4 a1 = *(const float4*)&As[cur][k][am_off + 4];
      float4 b0 = *(const float4*)&Bs[cur][k][bn_off];
      float4 b1 = *(const float4*)&Bs[cur][k][bn_off + 4];
      float af[8] = {a0.x, a0.y, a0.z, a0.w, a1.x, a1.y, a1.z, a1.w};
      float bf[8] = {b0.x, b0.y, b0.z, b0.w, b1.x, b1.y, b1.z, b1.w};
#pragma unroll
      for (int i = 0; i < 8; i++)
#pragma unroll
        for (int j = 0; j < 8; j++) acc[i][j] = fmaf(af[i], bf[j], acc[i][j]);
    }
    if (more) {
      As[nxtb][akg + 0][am] = ra0.x;
      As[nxtb][akg + 1][am] = ra0.y;
      As[nxtb][akg + 2][am] = ra0.z;
      As[nxtb][akg + 3][am] = ra0.w;
      As[nxtb][akg + 4][am] = ra1.x;
      As[nxtb][akg + 5][am] = ra1.y;
      As[nxtb][akg + 6][am] = ra1.z;
      As[nxtb][akg + 7][am] = ra1.w;
      CP_WAIT0();
    }
    __syncthreads();
  }

  float* base = g_D + (size_t)z * DSTRIDE;
#pragma unroll
  for (int i = 0; i < 8; i++) {
    const int mr = mt * 64 + am_off + i;
    float* dst = &base[(size_t)mr * CMID + n0 + bn_off];
    *(float4*)dst = make_float4(acc[i][0], acc[i][1], acc[i][2], acc[i][3]);
    *(float4*)(dst + 4) = make_float4(acc[i][4], acc[i][5], acc[i][6], acc[i][7]);
  }
}

// ---------------- K2: inverse transform Y = A^T M A + bias + relu ----------------
__global__ __launch_bounds__(256) void inv_kernel(const float* __restrict__ bias) {
  const int tile = blockIdx.x;
  const int n = threadIdx.x;
  const int ty = tile / NT1D, tx = tile % NT1D;
  const size_t off = (size_t)tile * CMID + n;
  float M[6][6];
#pragma unroll
  for (int i = 0; i < 6; i++)
#pragma unroll
    for (int j = 0; j < 6; j++) {
      const int xi = i * 6 + j;
      M[i][j] = g_D[(size_t)(xi * 4 + 0) * DSTRIDE + off] +
                g_D[(size_t)(xi * 4 + 1) * DSTRIDE + off] +
                g_D[(size_t)(xi * 4 + 2) * DSTRIDE + off] +
                g_D[(size_t)(xi * 4 + 3) * DSTRIDE + off];
    }
  float S[4][6];
#pragma unroll
  for (int j = 0; j < 6; j++) {
    S[0][j] = M[0][j] + M[1][j] + M[2][j] + M[3][j] + M[4][j];
    S[1][j] = M[1][j] - M[2][j] + 2.f * M[3][j] - 2.f * M[4][j];
    S[2][j] = M[1][j] + M[2][j] + 4.f * M[3][j] + 4.f * M[4][j];
    S[3][j] = M[1][j] - M[2][j] + 8.f * M[3][j] - 8.f * M[4][j] + M[5][j];
  }
  const float b = bias[n];
#pragma unroll
  for (int a = 0; a < 4; a++) {
    float y0 = S[a][0] + S[a][1] + S[a][2] + S[a][3] + S[a][4] + b;
    float y1 = S[a][1] - S[a][2] + 2.f * S[a][3] - 2.f * S[a][4] + b;
    float y2 = S[a][1] + S[a][2] + 4.f * S[a][3] + 4.f * S[a][4] + b;
    float y3 = S[a][1] - S[a][2] + 8.f * S[a][3] - 8.f * S[a][4] + S[a][5] + b;
    const int py = 4 * ty + a;
    const int px = 4 * tx;
    g_x[(size_t)(py * WW + px + 0) * CMID + n] = fmaxf(y0, 0.f);
    g_x[(size_t)(py * WW + px + 1) * CMID + n] = fmaxf(y1, 0.f);
    g_x[(size_t)(py * WW + px + 2) * CMID + n] = fmaxf(y2, 0.f);
    g_x[(size_t)(py * WW + px + 3) * CMID + n] = fmaxf(y3, 0.f);
  }
}

// ---------------- K3: 1x1 heads with transposed (coalesced) weights ----------------
__global__ __launch_bounds__(256) void head_conv_kernel(
    const float* __restrict__ cls_b, const float* __restrict__ reg_b) {
  const int p = blockIdx.x * 8 + (threadIdx.x >> 5);
  const int lane = threadIdx.x & 31;
  const float* xr = g_x + (size_t)p * CMID;
  float acc[30];
#pragma unroll
  for (int o = 0; o < 30; o++) acc[o] = 0.f;
#pragma unroll 1
  for (int k = lane; k < CMID; k += 32) {
    float xv = xr[k];
#pragma unroll
    for (int o = 0; o < 10; o++) acc[o] = fmaf(xv, g_wcT[o * CMID + k], acc[o]);
#pragma unroll
    for (int o = 0; o < 20; o++) acc[10 + o] = fmaf(xv, g_wrT[o * CMID + k], acc[10 + o]);
  }
#pragma unroll
  for (int o = 0; o < 30; o++) {
#pragma unroll
    for (int s = 16; s > 0; s >>= 1) acc[o] += __shfl_xor_sync(0xffffffffu, acc[o], s);
  }
  if (lane < NA) {
    const int a = lane;
    float l0 = acc[2 * a + 0] + cls_b[2 * a + 0];
    float l1 = acc[2 * a + 1] + cls_b[2 * a + 1];
    float score = 1.f / (1.f + expf(l0 - l1));
    float d0 = acc[10 + 4 * a + 0] + reg_b[4 * a + 0];
    float d1 = acc[10 + 4 * a + 1] + reg_b[4 * a + 1];
    float d2 = acc[10 + 4 * a + 2] + reg_b[4 * a + 2];
    float d3 = acc[10 + 4 * a + 3] + reg_b[4 * a + 3];
    float base = 32.f * (float)(1 << a);
    float wdt = expf(d2) * base;
    float hgt = expf(d3) * base;
    float xc = (float)(p % WW) + d0;
    float yc = (float)(p / WW) + d1;
    const int n = p * NA + a;
    g_scores[n] = score;
    float4 b = make_float4(xc - 0.5f * wdt, yc - 0.5f * hgt,
                           xc + 0.5f * wdt, yc + 0.5f * hgt);
    *(float4*)&g_boxes[n * 4] = b;
    g_rank[n] = 0;
  }
}

// ---------------- K4a: counting rank ----------------
__global__ __launch_bounds__(256) void rank_kernel() {
  __shared__ unsigned long long skey[1000];
  const int i = blockIdx.x * 256 + threadIdx.x;
  const int j0 = blockIdx.y * 1000;
  for (int jj = threadIdx.x; jj < 1000; jj += 256) skey[jj] = score_key(j0 + jj);
  __syncthreads();
  if (i < NBOX) {
    const unsigned long long mykey = score_key(i);
    int cnt = 0;
#pragma unroll 4
    for (int jj = 0; jj < 1000; jj++) cnt += (int)(skey[jj] < mykey);
    if (cnt) atomicAdd(&g_rank[i], cnt);
  }
}

// ---------------- K4b: scatter ----------------
__global__ __launch_bounds__(256) void scatter_kernel() {
  const int i = blockIdx.x * 256 + threadIdx.x;
  if (i < NBOX) {
    const int r = g_rank[i];
    *(float4*)&g_boxsorted[r * 4] = *(const float4*)&g_boxes[i * 4];
  }
}

// ---------------- K4c: IoU masks ----------------
__global__ __launch_bounds__(64) void mask_kernel() {
  const int cb = blockIdx.x, rb = blockIdx.y;
  const int tid = threadIdx.x;
  const int i = rb * 64 + tid;
  if (cb < rb) {
    g_mask[(size_t)i * NWORD + cb] = 0ull;
    return;
  }
  __shared__ float cx1[64], cy1[64], cx2[64], cy2[64], car[64];
  {
    const int j = cb * 64 + tid;
    float4 b = *(const float4*)&g_boxsorted[j * 4];
    cx1[tid] = b.x; cy1[tid] = b.y; cx2[tid] = b.z; cy2[tid] = b.w;
    car[tid] = (b.z - b.x) * (b.w - b.y);
  }
  __syncthreads();
  float4 bi = *(const float4*)&g_boxsorted[i * 4];
  const float ia = (bi.z - bi.x) * (bi.w - bi.y);
  unsigned long long w = 0ull;
#pragma unroll 4
  for (int jj = 0; jj < 64; jj++) {
    const int j = cb * 64 + jj;
    float iw = fmaxf(fminf(bi.z, cx2[jj]) - fmaxf(bi.x, cx1[jj]), 0.f);
    float ih = fmaxf(fminf(bi.w, cy2[jj]) - fmaxf(bi.y, cy1[jj]), 0.f);
    float inter = iw * ih;
    float iou = inter / (ia + car[jj] - inter);
    if (j > i && iou >= 0.7f) w |= (1ull << jj);
  }
  g_mask[(size_t)i * NWORD + cb] = w;
}

// ---------------- K5: chunked greedy scan, register-accumulated row ORs ----------------
__global__ __launch_bounds__(1024) void nms_scan_kernel() {
  extern __shared__ unsigned long long diag[];  // 8000 * 8B
  __shared__ unsigned long long remv[NWORD];
  __shared__ int ssel[MAXDET];
  __shared__ int keptl[64];
  const int tid = threadIdx.x;
  for (int j = tid; j < NBOX; j += 1024) diag[j] = g_mask[(size_t)j * NWORD + (j >> 6)];
  for (int w = tid; w < NWORD; w += 1024) remv[w] = 0ull;
  __syncthreads();
  if (tid >= 32) return;
  const int lane = tid;

  int count = 0;
#pragma unroll 1
  for (int c = 0; c < NWORD && count < MAXDET; c++) {
    int nk = 0;
    if (lane == 0) {
      unsigned long long avail = ~remv[c];
      while (avail && count < MAXDET) {
        const int b = __ffsll((long long)avail) - 1;
        const int j = (c << 6) + b;
        ssel[count++] = j;
        keptl[nk++] = j;
        avail &= ~(1ull << b);
        avail &= ~diag[j];
      }
    }
    nk = __shfl_sync(0xffffffffu, nk, 0);
    count = __shfl_sync(0xffffffffu, count, 0);
    __syncwarp();
    if (nk) {
      // accumulate kept rows in registers (independent loads -> MLP)
      unsigned long long racc[4] = {0ull, 0ull, 0ull, 0ull};
      for (int q = 0; q < nk; q++) {
        const unsigned long long* row = g_mask + (size_t)keptl[q] * NWORD;
#pragma unroll
        for (int b2 = 0; b2 < 4; b2++) {
          const int w = lane + b2 * 32;
          if (w > c && w < NWORD) racc[b2] |= row[w];
        }
      }
#pragma unroll
      for (int b2 = 0; b2 < 4; b2++) {
        const int w = lane + b2 * 32;
        if (w > c && w < NWORD) remv[w] |= racc[b2];
      }
    }
    __syncwarp();
  }
  for (int r = lane; r < MAXDET; r += 32) {
    float4 v = make_float4(0.f, 0.f, 0.f, 0.f);
    if (r < count) v = *(const float4*)&g_boxsorted[ssel[r] * 4];
    *(float4*)&g_rois[r * 4] = v;
  }
}

// ---------------- K6: FC head on 300 ROIs + final outputs ----------------
__global__ __launch_bounds__(128) void fc_head_kernel(
    const float* __restrict__ fc1_w, const float* __restrict__ fc1_b,
    const float* __restrict__ clsh_w, const float* __restrict__ clsh_b,
    const float* __restrict__ regh_w, const float* __restrict__ regh_b,
    float* __restrict__ out) {
  const int r = blockIdx.x;
  const int t = threadIdx.x;
  float4 roi = *(const float4*)&g_rois[r * 4];
  float part[8];
#pragma unroll
  for (int o = 0; o < 8; o++) part[o] = 0.f;
  for (int j = t; j < 1024; j += 128) {
    float f = fc1_b[j] + roi.x * fc1_w[j] + roi.y * fc1_w[1024 + j] +
              roi.z * fc1_w[2048 + j] + roi.w * fc1_w[3072 + j];
    f = fmaxf(f, 0.f);
    float4 cw = *(const float4*)&clsh_w[j * 4];
    float4 rw = *(const float4*)&regh_w[j * 4];
    part[0] += f * cw.x; part[1] += f * cw.y; part[2] += f * cw.z; part[3] += f * cw.w;
    part[4] += f * rw.x; part[5] += f * rw.y; part[6] += f * rw.z; part[7] += f * rw.w;
  }
#pragma unroll
  for (int o = 0; o < 8; o++) {
#pragma unroll
    for (int s = 16; s > 0; s >>= 1) part[o] += __shfl_xor_sync(0xffffffffu, part[o], s);
  }
  __shared__ float wred[4][8];
  const int warp = t >> 5, lane = t & 31;
  if (lane == 0) {
#pragma unroll
    for (int o = 0; o < 8; o++) wred[warp][o] = part[o];
  }
  __syncthreads();
  if (t == 0) {
    float v[8];
#pragma unroll
    for (int o = 0; o < 8; o++) v[o] = wred[0][o] + wred[1][o] + wred[2][o] + wred[3][o];
    float l0 = v[0] + clsh_b[0], l1 = v[1] + clsh_b[1];
    float l2 = v[2] + clsh_b[2], l3 = v[3] + clsh_b[3];
    float mx = fmaxf(fmaxf(l0, l1), fmaxf(l2, l3));
    float e0 = expf(l0 - mx), e1 = expf(l1 - mx), e2 = expf(l2 - mx), e3 = expf(l3 - mx);
    float inv = 1.f / (e0 + e1 + e2 + e3);
    out[r * 4 + 0] = e0 * inv;
    out[r * 4 + 1] = e1 * inv;
    out[r * 4 + 2] = e2 * inv;
    out[r * 4 + 3] = e3 * inv;
    out[1200 + r * 4 + 0] = v[4] + regh_b[0];
    out[1200 + r * 4 + 1] = v[5] + regh_b[1];
    out[1200 + r * 4 + 2] = v[6] + regh_b[2];
    out[1200 + r * 4 + 3] = v[7] + regh_b[3];
    *(float4*)&out[2400 + r * 4] = roi;
  }
}

// ---------------- launch ----------------
extern "C" void kernel_launch(void* const* d_in, const int* in_sizes, int n_in,
                              void* d_out, int out_size) {
  const float* feat   = (const float*)d_in[0];
  const float* conv_w = (const float*)d_in[1];
  const float* conv_b = (const float*)d_in[2];
  const float* cls_w  = (const float*)d_in[3];
  const float* cls_b  = (const float*)d_in[4];
  const float* reg_w  = (const float*)d_in[5];
  const float* reg_b  = (const float*)d_in[6];
  const float* fc1_w  = (const float*)d_in[7];
  const float* fc1_b  = (const float*)d_in[8];
  const float* clsh_w = (const float*)d_in[9];
  const float* clsh_b = (const float*)d_in[10];
  const float* regh_w = (const float*)d_in[11];
  const float* regh_b = (const float*)d_in[12];
  float* out = (float*)d_out;

  (void)in_sizes; (void)n_in; (void)out_size;

  cudaFuncSetAttribute(nms_scan_kernel, cudaFuncAttributeMaxDynamicSharedMemorySize,
                       NBOX * 8);

  transform_kernel<<<WT_BLOCKS + VT_BLOCKS + HP_BLOCKS, 256>>>(conv_w, feat, cls_w, reg_w);
  wino_gemm_kernel<<<dim3(2, 2, 144), 128>>>();
  inv_kernel<<<NTILE, 256>>>(conv_b);
  head_conv_kernel<<<200, 256>>>(cls_b, reg_b);
  rank_kernel<<<dim3(32, 8), 256>>>();
  scatter_kernel<<<(NBOX + 255) / 256, 256>>>();
  mask_kernel<<<dim3(NWORD, NWORD), 64>>>();
  nms_scan_kernel<<<1, 1024, NBOX * 8>>>();
  fc_head_kernel<<<300, 128>>>(fc1_w, fc1_b, clsh_w, clsh_b, regh_w, regh_b, out);
}

// round 14
// speedup vs baseline: 1.0273x; 1.0273x over previous
#include <cuda_runtime.h>
#include <math.h>
#include <stdint.h>

#define HH 40
#define WW 40
#define CIN 2048
#define NPIX 1600
#define CMID 256
#define NA 5
#define NBOX 8000
#define NWORD 125
#define MAXDET 300

#define NT1D 10
#define NTILE 100            // 10x10 F(4x4) tiles
#define VSTRIDE (NTILE * CIN)
#define KSTRIDE (CIN * CMID)
#define DSTRIDE (128 * CMID)
#define KC3 16
#define KPS 512
#define CHKS (KPS / KC3)     // 32

#define WT_BLOCKS ((CIN * CMID) / 256)   // 2048
#define VT_BLOCKS ((NTILE * CIN) / 256)  // 800
#define HP_BLOCKS 30                     // head-weight transpose

// head mini-GEMM smem layout (floats)
#define HSW_PITCH 257
#define HOFF_SW (64 * CMID)                     // 16384
#define HOFF_SOUT (HOFF_SW + 30 * HSW_PITCH + 2)  // aligned-ish
#define HSMEM_FLOATS (HOFF_SOUT + 64 * 32)
#define HSMEM_BYTES (HSMEM_FLOATS * 4)

// ---------------- device scratch (static, no allocation) ----------------
__device__ float g_Vt[36 * VSTRIDE];
__device__ float g_Wt[36 * KSTRIDE];
__device__ float g_D[144 * DSTRIDE];
__device__ float g_x[NPIX * CMID];
__device__ float g_wcT[10 * CMID];   // transposed cls_w [o][k]
__device__ float g_wrT[20 * CMID];   // transposed reg_w [o][k]
__device__ float g_scores[NBOX];
__device__ float g_boxes[NBOX * 4];
__device__ float g_boxsorted[NBOX * 4];
__device__ int g_rank[NBOX];
__device__ unsigned long long g_mask[(size_t)NBOX * NWORD];
__device__ float g_rois[MAXDET * 4];

__device__ __forceinline__ uint32_t smem_u32(const void* p) {
  uint32_t a;
  asm("{ .reg .u64 t; cvta.to.shared.u64 t, %1; cvt.u32.u64 %0, t; }" : "=r"(a) : "l"(p));
  return a;
}
__device__ __forceinline__ void cp16(uint32_t dst, const void* src) {
  asm volatile("cp.async.ca.shared.global [%0], [%1], 16;" ::"r"(dst), "l"(src) : "memory");
}
#define CP_COMMIT() asm volatile("cp.async.commit_group;" ::: "memory")
#define CP_WAIT0() asm volatile("cp.async.wait_group 0;" ::: "memory")

__device__ __forceinline__ unsigned long long score_key(int i) {
  uint32_t u = __float_as_uint(g_scores[i]);
  uint32_t ou = (u & 0x80000000u) ? ~u : (u | 0x80000000u);
  return ((unsigned long long)(~ou) << 13) | (unsigned)i;
}

// ---------------- K0: fused transforms ----------------
__device__ __forceinline__ void wt_body(const float* __restrict__ w, int blk) {
  const int idx = blk * 256 + threadIdx.x;
  float g[3][3];
#pragma unroll
  for (int i = 0; i < 3; i++)
#pragma unroll
    for (int j = 0; j < 3; j++) g[i][j] = w[(size_t)(i * 3 + j) * KSTRIDE + idx];
  float T[6][3];
#pragma unroll
  for (int j = 0; j < 3; j++) {
    T[0][j] = 0.25f * g[0][j];
    T[1][j] = -0.16666667f * (g[0][j] + g[1][j] + g[2][j]);
    T[2][j] = 0.16666667f * (-g[0][j] + g[1][j] - g[2][j]);
    T[3][j] = 0.041666668f * g[0][j] + 0.083333336f * g[1][j] + 0.16666667f * g[2][j];
    T[4][j] = 0.041666668f * g[0][j] - 0.083333336f * g[1][j] + 0.16666667f * g[2][j];
    T[5][j] = g[2][j];
  }
#pragma unroll
  for (int i = 0; i < 6; i++) {
    float u[6];
    u[0] = 0.25f * T[i][0];
    u[1] = -0.16666667f * (T[i][0] + T[i][1] + T[i][2]);
    u[2] = 0.16666667f * (-T[i][0] + T[i][1] - T[i][2]);
    u[3] = 0.041666668f * T[i][0] + 0.083333336f * T[i][1] + 0.16666667f * T[i][2];
    u[4] = 0.041666668f * T[i][0] - 0.083333336f * T[i][1] + 0.16666667f * T[i][2];
    u[5] = T[i][2];
#pragma unroll
    for (int j = 0; j < 6; j++)
      g_Wt[(size_t)(i * 6 + j) * KSTRIDE + idx] = u[j];
  }
}

__device__ __forceinline__ void vt_body(const float* __restrict__ feat, int blk) {
  const int idx = blk * 256 + threadIdx.x;
  const int tile = idx >> 11, k = idx & 2047;
  const int ty = tile / NT1D, tx = tile % NT1D;
  const int oy = 4 * ty - 1, ox = 4 * tx - 1;
  float d[6][6];
#pragma unroll
  for (int i = 0; i < 6; i++) {
    const int py = oy + i;
    const bool yok = (py >= 0 && py < HH);
#pragma unroll
    for (int j = 0; j < 6; j++) {
      const int px = ox + j;
      d[i][j] = (yok && px >= 0 && px < WW)
                    ? feat[(size_t)(py * WW + px) * CIN + k] : 0.f;
    }
  }
  float t[6][6];
#pragma unroll
  for (int j = 0; j < 6; j++) {
    t[0][j] = 4.f * d[0][j] - 5.f * d[2][j] + d[4][j];
    t[1][j] = -4.f * d[1][j] - 4.f * d[2][j] + d[3][j] + d[4][j];
    t[2][j] = 4.f * d[1][j] - 4.f * d[2][j] - d[3][j] + d[4][j];
    t[3][j] = -2.f * d[1][j] - d[2][j] + 2.f * d[3][j] + d[4][j];
    t[4][j] = 2.f * d[1][j] - d[2][j] - 2.f * d[3][j] + d[4][j];
    t[5][j] = 4.f * d[1][j] - 5.f * d[3][j] + d[5][j];
  }
  const size_t base = (size_t)tile * CIN + k;
#pragma unroll
  for (int i = 0; i < 6; i++) {
    float v[6];
    v[0] = 4.f * t[i][0] - 5.f * t[i][2] + t[i][4];
    v[1] = -4.f * t[i][1] - 4.f * t[i][2] + t[i][3] + t[i][4];
    v[2] = 4.f * t[i][1] - 4.f * t[i][2] - t[i][3] + t[i][4];
    v[3] = -2.f * t[i][1] - t[i][2] + 2.f * t[i][3] + t[i][4];
    v[4] = 2.f * t[i][1] - t[i][2] - 2.f * t[i][3] + t[i][4];
    v[5] = 4.f * t[i][1] - 5.f * t[i][3] + t[i][5];
#pragma unroll
    for (int j = 0; j < 6; j++)
      g_Vt[(size_t)(i * 6 + j) * VSTRIDE + base] = v[j];
  }
}

__device__ __forceinline__ void hp_body(const float* __restrict__ cls_w,
                                        const float* __restrict__ reg_w, int blk) {
  const int idx = blk * 256 + threadIdx.x;
  if (idx < 10 * CMID) {
    const int o = idx >> 8, k = idx & 255;
    g_wcT[idx] = cls_w[k * 10 + o];
  } else if (idx < 30 * CMID) {
    const int i2 = idx - 10 * CMID;
    const int o = i2 >> 8, k = i2 & 255;
    g_wrT[i2] = reg_w[k * 20 + o];
  }
}

__global__ __launch_bounds__(256) void transform_kernel(const float* __restrict__ w,
                                                        const float* __restrict__ feat,
                                                        const float* __restrict__ cls_w,
                                                        const float* __restrict__ reg_w) {
  const int b = blockIdx.x;
  if (b < WT_BLOCKS) wt_body(w, b);
  else if (b < WT_BLOCKS + VT_BLOCKS) vt_body(feat, b - WT_BLOCKS);
  else hp_body(cls_w, reg_w, b - WT_BLOCKS - VT_BLOCKS);
}

// ---------------- K1: winograd GEMM, 64x128 tile, 8x8/thread ----------------
__global__ __launch_bounds__(128) void wino_gemm_kernel() {
  __shared__ __align__(16) float As[2][KC3][64];
  __shared__ __align__(16) float Bs[2][KC3][128];

  const int mt = blockIdx.x;
  const int nt = blockIdx.y;
  const int z = blockIdx.z;
  const int xi = z >> 2;
  const int ks = z & 3;
  const int tid = threadIdx.x;
  const int warp = tid >> 5;
  const int lane = tid & 31;
  const int rg = lane >> 2;
  const int cg = lane & 3;
  const int am_off = rg * 8;
  const int bn_off = warp * 32 + cg * 8;

  const int am = tid & 63;
  const int akg = (tid >> 6) * 8;
  const int m = mt * 64 + am;
  const bool aval = (m < NTILE);
  const float* arow =
      g_Vt + (size_t)xi * VSTRIDE + (size_t)(aval ? m : 0) * CIN + ks * KPS + akg;

  const int bk = tid >> 3;
  const int bn = (tid & 7) * 16;
  const int n0 = nt * 128;
  const float* bsrc = g_Wt + (size_t)xi * KSTRIDE + (size_t)(ks * KPS + bk) * CMID + n0 + bn;

  float acc[8][8];
#pragma unroll
  for (int i = 0; i < 8; i++)
#pragma unroll
    for (int j = 0; j < 8; j++) acc[i][j] = 0.f;

  {
    float4 ra0 = aval ? *(const float4*)arow : make_float4(0.f, 0.f, 0.f, 0.f);
    float4 ra1 = aval ? *(const float4*)(arow + 4) : make_float4(0.f, 0.f, 0.f, 0.f);
#pragma unroll
    for (int i = 0; i < 4; i++) cp16(smem_u32(&Bs[0][bk][bn + i * 4]), bsrc + i * 4);
    CP_COMMIT();
    As[0][akg + 0][am] = ra0.x;
    As[0][akg + 1][am] = ra0.y;
    As[0][akg + 2][am] = ra0.z;
    As[0][akg + 3][am] = ra0.w;
    As[0][akg + 4][am] = ra1.x;
    As[0][akg + 5][am] = ra1.y;
    As[0][akg + 6][am] = ra1.z;
    As[0][akg + 7][am] = ra1.w;
    CP_WAIT0();
  }
  __syncthreads();

#pragma unroll 1
  for (int c = 0; c < CHKS; c++) {
    const int cur = c & 1;
    const int nxtb = cur ^ 1;
    float4 ra0, ra1;
    const bool more = (c + 1 < CHKS);
    if (more) {
      const int k0 = (c + 1) * KC3;
      ra0 = aval ? *(const float4*)(arow + k0) : make_float4(0.f, 0.f, 0.f, 0.f);
      ra1 = aval ? *(const float4*)(arow + k0 + 4) : make_float4(0.f, 0.f, 0.f, 0.f);
      const float* bs = bsrc + (size_t)k0 * CMID;
#pragma unroll
      for (int i = 0; i < 4; i++) cp16(smem_u32(&Bs[nxtb][bk][bn + i * 4]), bs + i * 4);
      CP_COMMIT();
    }
#pragma unroll
    for (int k = 0; k < KC3; k++) {
      float4 a0 = *(const float4*)&As[cur][k][am_off];
      float4 a1 = *(const float4*)&As[cur][k][am_off + 4];
      float4 b0 = *(const float4*)&Bs[cur][k][bn_off];
      float4 b1 = *(const float4*)&Bs[cur][k][bn_off + 4];
      float af[8] = {a0.x, a0.y, a0.z, a0.w, a1.x, a1.y, a1.z, a1.w};
      float bf[8] = {b0.x, b0.y, b0.z, b0.w, b1.x, b1.y, b1.z, b1.w};
#pragma unroll
      for (int i = 0; i < 8; i++)
#pragma unroll
        for (int j = 0; j < 8; j++) acc[i][j] = fmaf(af[i], bf[j], acc[i][j]);
    }
    if (more) {
      As[nxtb][akg + 0][am] = ra0.x;
      As[nxtb][akg + 1][am] = ra0.y;
      As[nxtb][akg + 2][am] = ra0.z;
      As[nxtb][akg + 3][am] = ra0.w;
      As[nxtb][akg + 4][am] = ra1.x;
      As[nxtb][akg + 5][am] = ra1.y;
      As[nxtb][akg + 6][am] = ra1.z;
      As[nxtb][akg + 7][am] = ra1.w;
      CP_WAIT0();
    }
    __syncthreads();
  }

  float* base = g_D + (size_t)z * DSTRIDE;
#pragma unroll
  for (int i = 0; i < 8; i++) {
    const int mr = mt * 64 + am_off + i;
    float* dst = &base[(size_t)mr * CMID + n0 + bn_off];
    *(float4*)dst = make_float4(acc[i][0], acc[i][1], acc[i][2], acc[i][3]);
    *(float4*)(dst + 4) = make_float4(acc[i][4], acc[i][5], acc[i][6], acc[i][7]);
  }
}

// ---------------- K2: inverse transform Y = A^T M A + bias + relu ----------------
__global__ __launch_bounds__(256) void inv_kernel(const float* __restrict__ bias) {
  const int tile = blockIdx.x;
  const int n = threadIdx.x;
  const int ty = tile / NT1D, tx = tile % NT1D;
  const size_t off = (size_t)tile * CMID + n;
  float M[6][6];
#pragma unroll
  for (int i = 0; i < 6; i++)
#pragma unroll
    for (int j = 0; j < 6; j++) {
      const int xi = i * 6 + j;
      M[i][j] = g_D[(size_t)(xi * 4 + 0) * DSTRIDE + off] +
                g_D[(size_t)(xi * 4 + 1) * DSTRIDE + off] +
                g_D[(size_t)(xi * 4 + 2) * DSTRIDE + off] +
                g_D[(size_t)(xi * 4 + 3) * DSTRIDE + off];
    }
  float S[4][6];
#pragma unroll
  for (int j = 0; j < 6; j++) {
    S[0][j] = M[0][j] + M[1][j] + M[2][j] + M[3][j] + M[4][j];
    S[1][j] = M[1][j] - M[2][j] + 2.f * M[3][j] - 2.f * M[4][j];
    S[2][j] = M[1][j] + M[2][j] + 4.f * M[3][j] + 4.f * M[4][j];
    S[3][j] = M[1][j] - M[2][j] + 8.f * M[3][j] - 8.f * M[4][j] + M[5][j];
  }
  const float b = bias[n];
#pragma unroll
  for (int a = 0; a < 4; a++) {
    float y0 = S[a][0] + S[a][1] + S[a][2] + S[a][3] + S[a][4] + b;
    float y1 = S[a][1] - S[a][2] + 2.f * S[a][3] - 2.f * S[a][4] + b;
    float y2 = S[a][1] + S[a][2] + 4.f * S[a][3] + 4.f * S[a][4] + b;
    float y3 = S[a][1] - S[a][2] + 8.f * S[a][3] - 8.f * S[a][4] + S[a][5] + b;
    const int py = 4 * ty + a;
    const int px = 4 * tx;
    g_x[(size_t)(py * WW + px + 0) * CMID + n] = fmaxf(y0, 0.f);
    g_x[(size_t)(py * WW + px + 1) * CMID + n] = fmaxf(y1, 0.f);
    g_x[(size_t)(py * WW + px + 2) * CMID + n] = fmaxf(y2, 0.f);
    g_x[(size_t)(py * WW + px + 3) * CMID + n] = fmaxf(y3, 0.f);
  }
}

// ---------------- K3: head as smem mini-GEMM (64 pixels/block, grid 25) ----------------
__global__ __launch_bounds__(256) void head_conv_kernel(
    const float* __restrict__ cls_b, const float* __restrict__ reg_b) {
  extern __shared__ float hs[];  // sx[64][256] | sw[30][257] | sout[64][32]
  float* sx = hs;
  float* sw = hs + HOFF_SW;
  float* sout = hs + HOFF_SOUT;
  const int tid = threadIdx.x;
  const int p0 = blockIdx.x * 64;

  // stage x tile (coalesced: consecutive tid -> consecutive k)
  {
    const float* src = g_x + (size_t)p0 * CMID;
    const float4* s4 = (const float4*)src;
    float4* d4 = (float4*)sx;
    for (int i = tid; i < 64 * CMID / 4; i += 256) d4[i] = s4[i];
  }
  // stage transposed head weights with pitch 257 (conflict-free)
  for (int i = tid; i < 30 * CMID; i += 256) {
    const int o = i >> 8, k = i & 255;
    sw[o * HSW_PITCH + k] = (o < 10) ? g_wcT[i] : g_wrT[i - 10 * CMID];
  }
  __syncthreads();

  // mini-GEMM: warp w -> pixels w*8..w*8+7 ; lane n -> output n (n<30)
  const int warp = tid >> 5;
  const int n = tid & 31;
  float acc[8];
#pragma unroll
  for (int m = 0; m < 8; m++) acc[m] = 0.f;
  const float* wrow = sw + n * HSW_PITCH;
#pragma unroll 1
  for (int k0 = 0; k0 < CMID; k0 += 4) {
    const float w0 = wrow[k0], w1 = wrow[k0 + 1], w2 = wrow[k0 + 2], w3 = wrow[k0 + 3];
#pragma unroll
    for (int m = 0; m < 8; m++) {
      float4 xv = *(const float4*)&sx[(warp * 8 + m) * CMID + k0];
      acc[m] = fmaf(xv.x, w0, acc[m]);
      acc[m] = fmaf(xv.y, w1, acc[m]);
      acc[m] = fmaf(xv.z, w2, acc[m]);
      acc[m] = fmaf(xv.w, w3, acc[m]);
    }
  }
  if (n < 30) {
#pragma unroll
    for (int m = 0; m < 8; m++) sout[(warp * 8 + m) * 32 + n] = acc[m];
  }
  __syncthreads();

  // finalize: 64 pixels x 5 anchors
  for (int idx = tid; idx < 64 * NA; idx += 256) {
    const int lp = idx / NA, a = idx % NA;
    const float* so = sout + lp * 32;
    const int p = p0 + lp;
    float l0 = so[2 * a + 0] + cls_b[2 * a + 0];
    float l1 = so[2 * a + 1] + cls_b[2 * a + 1];
    float score = 1.f / (1.f + expf(l0 - l1));
    float d0 = so[10 + 4 * a + 0] + reg_b[4 * a + 0];
    float d1 = so[10 + 4 * a + 1] + reg_b[4 * a + 1];
    float d2 = so[10 + 4 * a + 2] + reg_b[4 * a + 2];
    float d3 = so[10 + 4 * a + 3] + reg_b[4 * a + 3];
    float base = 32.f * (float)(1 << a);
    float wdt = expf(d2) * base;
    float hgt = expf(d3) * base;
    float xc = (float)(p % WW) + d0;
    float yc = (float)(p / WW) + d1;
    const int bn = p * NA + a;
    g_scores[bn] = score;
    float4 b = make_float4(xc - 0.5f * wdt, yc - 0.5f * hgt,
                           xc + 0.5f * wdt, yc + 0.5f * hgt);
    *(float4*)&g_boxes[bn * 4] = b;
    g_rank[bn] = 0;
  }
}

// ---------------- K4a: counting rank ----------------
__global__ __launch_bounds__(256) void rank_kernel() {
  __shared__ unsigned long long skey[1000];
  const int i = blockIdx.x * 256 + threadIdx.x;
  const int j0 = blockIdx.y * 1000;
  for (int jj = threadIdx.x; jj < 1000; jj += 256) skey[jj] = score_key(j0 + jj);
  __syncthreads();
  if (i < NBOX) {
    const unsigned long long mykey = score_key(i);
    int cnt = 0;
#pragma unroll 4
    for (int jj = 0; jj < 1000; jj++) cnt += (int)(skey[jj] < mykey);
    if (cnt) atomicAdd(&g_rank[i], cnt);
  }
}

// ---------------- K4b: scatter ----------------
__global__ __launch_bounds__(256) void scatter_kernel() {
  const int i = blockIdx.x * 256 + threadIdx.x;
  if (i < NBOX) {
    const int r = g_rank[i];
    *(float4*)&g_boxsorted[r * 4] = *(const float4*)&g_boxes[i * 4];
  }
}

// ---------------- K4c: IoU masks ----------------
__global__ __launch_bounds__(64) void mask_kernel() {
  const int cb = blockIdx.x, rb = blockIdx.y;
  const int tid = threadIdx.x;
  const int i = rb * 64 + tid;
  if (cb < rb) {
    g_mask[(size_t)i * NWORD + cb] = 0ull;
    return;
  }
  __shared__ float cx1[64], cy1[64], cx2[64], cy2[64], car[64];
  {
    const int j = cb * 64 + tid;
    float4 b = *(const float4*)&g_boxsorted[j * 4];
    cx1[tid] = b.x; cy1[tid] = b.y; cx2[tid] = b.z; cy2[tid] = b.w;
    car[tid] = (b.z - b.x) * (b.w - b.y);
  }
  __syncthreads();
  float4 bi = *(const float4*)&g_boxsorted[i * 4];
  const float ia = (bi.z - bi.x) * (bi.w - bi.y);
  unsigned long long w = 0ull;
#pragma unroll 4
  for (int jj = 0; jj < 64; jj++) {
    const int j = cb * 64 + jj;
    float iw = fmaxf(fminf(bi.z, cx2[jj]) - fmaxf(bi.x, cx1[jj]), 0.f);
    float ih = fmaxf(fminf(bi.w, cy2[jj]) - fmaxf(bi.y, cy1[jj]), 0.f);
    float inter = iw * ih;
    float iou = inter / (ia + car[jj] - inter);
    if (j > i && iou >= 0.7f) w |= (1ull << jj);
  }
  g_mask[(size_t)i * NWORD + cb] = w;
}

// ---------------- K5: chunked greedy scan, register-accumulated row ORs ----------------
__global__ __launch_bounds__(1024) void nms_scan_kernel() {
  extern __shared__ unsigned long long diag[];
  __shared__ unsigned long long remv[NWORD];
  __shared__ int ssel[MAXDET];
  __shared__ int keptl[64];
  const int tid = threadIdx.x;
  for (int j = tid; j < NBOX; j += 1024) diag[j] = g_mask[(size_t)j * NWORD + (j >> 6)];
  for (int w = tid; w < NWORD; w += 1024) remv[w] = 0ull;
  __syncthreads();
  if (tid >= 32) return;
  const int lane = tid;

  int count = 0;
#pragma unroll 1
  for (int c = 0; c < NWORD && count < MAXDET; c++) {
    int nk = 0;
    if (lane == 0) {
      unsigned long long avail = ~remv[c];
      while (avail && count < MAXDET) {
        const int b = __ffsll((long long)avail) - 1;
        const int j = (c << 6) + b;
        ssel[count++] = j;
        keptl[nk++] = j;
        avail &= ~(1ull << b);
        avail &= ~diag[j];
      }
    }
    nk = __shfl_sync(0xffffffffu, nk, 0);
    count = __shfl_sync(0xffffffffu, count, 0);
    __syncwarp();
    if (nk) {
      unsigned long long racc[4] = {0ull, 0ull, 0ull, 0ull};
      for (int q = 0; q < nk; q++) {
        const unsigned long long* row = g_mask + (size_t)keptl[q] * NWORD;
#pragma unroll
        for (int b2 = 0; b2 < 4; b2++) {
          const int w = lane + b2 * 32;
          if (w > c && w < NWORD) racc[b2] |= row[w];
        }
      }
#pragma unroll
      for (int b2 = 0; b2 < 4; b2++) {
        const int w = lane + b2 * 32;
        if (w > c && w < NWORD) remv[w] |= racc[b2];
      }
    }
    __syncwarp();
  }
  for (int r = lane; r < MAXDET; r += 32) {
    float4 v = make_float4(0.f, 0.f, 0.f, 0.f);
    if (r < count) v = *(const float4*)&g_boxsorted[ssel[r] * 4];
    *(float4*)&g_rois[r * 4] = v;
  }
}

// ---------------- K6: FC head on 300 ROIs + final outputs ----------------
__global__ __launch_bounds__(128) void fc_head_kernel(
    const float* __restrict__ fc1_w, const float* __restrict__ fc1_b,
    const float* __restrict__ clsh_w, const float* __restrict__ clsh_b,
    const float* __restrict__ regh_w, const float* __restrict__ regh_b,
    float* __restrict__ out) {
  const int r = blockIdx.x;
  const int t = threadIdx.x;
  float4 roi = *(const float4*)&g_rois[r * 4];
  float part[8];
#pragma unroll
  for (int o = 0; o < 8; o++) part[o] = 0.f;
  for (int j = t; j < 1024; j += 128) {
    float f = fc1_b[j] + roi.x * fc1_w[j] + roi.y * fc1_w[1024 + j] +
              roi.z * fc1_w[2048 + j] + roi.w * fc1_w[3072 + j];
    f = fmaxf(f, 0.f);
    float4 cw = *(const float4*)&clsh_w[j * 4];
    float4 rw = *(const float4*)&regh_w[j * 4];
    part[0] += f * cw.x; part[1] += f * cw.y; part[2] += f * cw.z; part[3] += f * cw.w;
    part[4] += f * rw.x; part[5] += f * rw.y; part[6] += f * rw.z; part[7] += f * rw.w;
  }
#pragma unroll
  for (int o = 0; o < 8; o++) {
#pragma unroll
    for (int s = 16; s > 0; s >>= 1) part[o] += __shfl_xor_sync(0xffffffffu, part[o], s);
  }
  __shared__ float wred[4][8];
  const int warp = t >> 5, lane = t & 31;
  if (lane == 0) {
#pragma unroll
    for (int o = 0; o < 8; o++) wred[warp][o] = part[o];
  }
  __syncthreads();
  if (t == 0) {
    float v[8];
#pragma unroll
    for (int o = 0; o < 8; o++) v[o] = wred[0][o] + wred[1][o] + wred[2][o] + wred[3][o];
    float l0 = v[0] + clsh_b[0], l1 = v[1] + clsh_b[1];
    float l2 = v[2] + clsh_b[2], l3 = v[3] + clsh_b[3];
    float mx = fmaxf(fmaxf(l0, l1), fmaxf(l2, l3));
    float e0 = expf(l0 - mx), e1 = expf(l1 - mx), e2 = expf(l2 - mx), e3 = expf(l3 - mx);
    float inv = 1.f / (e0 + e1 + e2 + e3);
    out[r * 4 + 0] = e0 * inv;
    out[r * 4 + 1] = e1 * inv;
    out[r * 4 + 2] = e2 * inv;
    out[r * 4 + 3] = e3 * inv;
    out[1200 + r * 4 + 0] = v[4] + regh_b[0];
    out[1200 + r * 4 + 1] = v[5] + regh_b[1];
    out[1200 + r * 4 + 2] = v[6] + regh_b[2];
    out[1200 + r * 4 + 3] = v[7] + regh_b[3];
    *(float4*)&out[2400 + r * 4] = roi;
  }
}

// ---------------- launch ----------------
extern "C" void kernel_launch(void* const* d_in, const int* in_sizes, int n_in,
                              void* d_out, int out_size) {
  const float* feat   = (const float*)d_in[0];
  const float* conv_w = (const float*)d_in[1];
  const float* conv_b = (const float*)d_in[2];
  const float* cls_w  = (const float*)d_in[3];
  const float* cls_b  = (const float*)d_in[4];
  const float* reg_w  = (const float*)d_in[5];
  const float* reg_b  = (const float*)d_in[6];
  const float* fc1_w  = (const float*)d_in[7];
  const float* fc1_b  = (const float*)d_in[8];
  const float* clsh_w = (const float*)d_in[9];
  const float* clsh_b = (const float*)d_in[10];
  const float* regh_w = (const float*)d_in[11];
  const float* regh_b = (const float*)d_in[12];
  float* out = (float*)d_out;

  (void)in_sizes; (void)n_in; (void)out_size;

  cudaFuncSetAttribute(nms_scan_kernel, cudaFuncAttributeMaxDynamicSharedMemorySize,
                       NBOX * 8);
  cudaFuncSetAttribute(head_conv_kernel, cudaFuncAttributeMaxDynamicSharedMemorySize,
                       HSMEM_BYTES);

  transform_kernel<<<WT_BLOCKS + VT_BLOCKS + HP_BLOCKS, 256>>>(conv_w, feat, cls_w, reg_w);
  wino_gemm_kernel<<<dim3(2, 2, 144), 128>>>();
  inv_kernel<<<NTILE, 256>>>(conv_b);
  head_conv_kernel<<<25, 256, HSMEM_BYTES>>>(cls_b, reg_b);
  rank_kernel<<<dim3(32, 8), 256>>>();
  scatter_kernel<<<(NBOX + 255) / 256, 256>>>();
  mask_kernel<<<dim3(NWORD, NWORD), 64>>>();
  nms_scan_kernel<<<1, 1024, NBOX * 8>>>();
  fc_head_kernel<<<300, 128>>>(fc1_w, fc1_b, clsh_w, clsh_b, regh_w, regh_b, out);
}

// round 15
// speedup vs baseline: 1.0629x; 1.0347x over previous
#include <cuda_runtime.h>
#include <math.h>
#include <stdint.h>

#define HH 40
#define WW 40
#define CIN 2048
#define NPIX 1600
#define CMID 256
#define NA 5
#define NBOX 8000
#define NWORD 125
#define MAXDET 300

#define NT1D 10
#define NTILE 100
#define VSTRIDE (NTILE * CIN)
#define KSTRIDE (CIN * CMID)
#define DSTRIDE (128 * CMID)
#define KC3 16
#define KPS 512
#define CHKS (KPS / KC3)

#define WT_BLOCKS ((CIN * CMID) / 256)
#define VT_BLOCKS ((NTILE * CIN) / 256)
#define HP_BLOCKS 30

// head mini-GEMM smem layout (floats): sx[16][256] | sw[30][257] | sout[16][32]
#define HSW_PITCH 257
#define HOFF_SW (16 * CMID)
#define HOFF_SOUT (HOFF_SW + 30 * HSW_PITCH + 2)
#define HSMEM_FLOATS (HOFF_SOUT + 16 * 32)
#define HSMEM_BYTES (HSMEM_FLOATS * 4)

// ---------------- device scratch ----------------
__device__ float g_Vt[36 * VSTRIDE];
__device__ float g_Wt[36 * KSTRIDE];
__device__ float g_D[144 * DSTRIDE];
__device__ float g_x[NPIX * CMID];
__device__ float g_wcT[10 * CMID];
__device__ float g_wrT[20 * CMID];
__device__ float g_scores[NBOX];
__device__ float g_boxes[NBOX * 4];
__device__ float g_boxsorted[NBOX * 4];
__device__ int g_rank[NBOX];
__device__ unsigned long long g_mask[(size_t)NBOX * NWORD];
__device__ float g_rois[MAXDET * 4];

__device__ __forceinline__ uint32_t smem_u32(const void* p) {
  uint32_t a;
  asm("{ .reg .u64 t; cvta.to.shared.u64 t, %1; cvt.u32.u64 %0, t; }" : "=r"(a) : "l"(p));
  return a;
}
__device__ __forceinline__ void cp16(uint32_t dst, const void* src) {
  asm volatile("cp.async.ca.shared.global [%0], [%1], 16;" ::"r"(dst), "l"(src) : "memory");
}
#define CP_COMMIT() asm volatile("cp.async.commit_group;" ::: "memory")
#define CP_WAIT0() asm volatile("cp.async.wait_group 0;" ::: "memory")

__device__ __forceinline__ unsigned long long score_key(int i) {
  uint32_t u = __float_as_uint(g_scores[i]);
  uint32_t ou = (u & 0x80000000u) ? ~u : (u | 0x80000000u);
  return ((unsigned long long)(~ou) << 13) | (unsigned)i;
}

// ---------------- K0: fused transforms ----------------
__device__ __forceinline__ void wt_body(const float* __restrict__ w, int blk) {
  const int idx = blk * 256 + threadIdx.x;
  float g[3][3];
#pragma unroll
  for (int i = 0; i < 3; i++)
#pragma unroll
    for (int j = 0; j < 3; j++) g[i][j] = w[(size_t)(i * 3 + j) * KSTRIDE + idx];
  float T[6][3];
#pragma unroll
  for (int j = 0; j < 3; j++) {
    T[0][j] = 0.25f * g[0][j];
    T[1][j] = -0.16666667f * (g[0][j] + g[1][j] + g[2][j]);
    T[2][j] = 0.16666667f * (-g[0][j] + g[1][j] - g[2][j]);
    T[3][j] = 0.041666668f * g[0][j] + 0.083333336f * g[1][j] + 0.16666667f * g[2][j];
    T[4][j] = 0.041666668f * g[0][j] - 0.083333336f * g[1][j] + 0.16666667f * g[2][j];
    T[5][j] = g[2][j];
  }
#pragma unroll
  for (int i = 0; i < 6; i++) {
    float u[6];
    u[0] = 0.25f * T[i][0];
    u[1] = -0.16666667f * (T[i][0] + T[i][1] + T[i][2]);
    u[2] = 0.16666667f * (-T[i][0] + T[i][1] - T[i][2]);
    u[3] = 0.041666668f * T[i][0] + 0.083333336f * T[i][1] + 0.16666667f * T[i][2];
    u[4] = 0.041666668f * T[i][0] - 0.083333336f * T[i][1] + 0.16666667f * T[i][2];
    u[5] = T[i][2];
#pragma unroll
    for (int j = 0; j < 6; j++)
      g_Wt[(size_t)(i * 6 + j) * KSTRIDE + idx] = u[j];
  }
}

__device__ __forceinline__ void vt_body(const float* __restrict__ feat, int blk) {
  const int idx = blk * 256 + threadIdx.x;
  const int tile = idx >> 11, k = idx & 2047;
  const int ty = tile / NT1D, tx = tile % NT1D;
  const int oy = 4 * ty - 1, ox = 4 * tx - 1;
  float d[6][6];
#pragma unroll
  for (int i = 0; i < 6; i++) {
    const int py = oy + i;
    const bool yok = (py >= 0 && py < HH);
#pragma unroll
    for (int j = 0; j < 6; j++) {
      const int px = ox + j;
      d[i][j] = (yok && px >= 0 && px < WW)
                    ? feat[(size_t)(py * WW + px) * CIN + k] : 0.f;
    }
  }
  float t[6][6];
#pragma unroll
  for (int j = 0; j < 6; j++) {
    t[0][j] = 4.f * d[0][j] - 5.f * d[2][j] + d[4][j];
    t[1][j] = -4.f * d[1][j] - 4.f * d[2][j] + d[3][j] + d[4][j];
    t[2][j] = 4.f * d[1][j] - 4.f * d[2][j] - d[3][j] + d[4][j];
    t[3][j] = -2.f * d[1][j] - d[2][j] + 2.f * d[3][j] + d[4][j];
    t[4][j] = 2.f * d[1][j] - d[2][j] - 2.f * d[3][j] + d[4][j];
    t[5][j] = 4.f * d[1][j] - 5.f * d[3][j] + d[5][j];
  }
  const size_t base = (size_t)tile * CIN + k;
#pragma unroll
  for (int i = 0; i < 6; i++) {
    float v[6];
    v[0] = 4.f * t[i][0] - 5.f * t[i][2] + t[i][4];
    v[1] = -4.f * t[i][1] - 4.f * t[i][2] + t[i][3] + t[i][4];
    v[2] = 4.f * t[i][1] - 4.f * t[i][2] - t[i][3] + t[i][4];
    v[3] = -2.f * t[i][1] - t[i][2] + 2.f * t[i][3] + t[i][4];
    v[4] = 2.f * t[i][1] - t[i][2] - 2.f * t[i][3] + t[i][4];
    v[5] = 4.f * t[i][1] - 5.f * t[i][3] + t[i][5];
#pragma unroll
    for (int j = 0; j < 6; j++)
      g_Vt[(size_t)(i * 6 + j) * VSTRIDE + base] = v[j];
  }
}

__device__ __forceinline__ void hp_body(const float* __restrict__ cls_w,
                                        const float* __restrict__ reg_w, int blk) {
  const int idx = blk * 256 + threadIdx.x;
  if (idx < 10 * CMID) {
    const int o = idx >> 8, k = idx & 255;
    g_wcT[idx] = cls_w[k * 10 + o];
  } else if (idx < 30 * CMID) {
    const int i2 = idx - 10 * CMID;
    const int o = i2 >> 8, k = i2 & 255;
    g_wrT[i2] = reg_w[k * 20 + o];
  }
}

__global__ __launch_bounds__(256) void transform_kernel(const float* __restrict__ w,
                                                        const float* __restrict__ feat,
                                                        const float* __restrict__ cls_w,
                                                        const float* __restrict__ reg_w) {
  const int b = blockIdx.x;
  if (b < WT_BLOCKS) wt_body(w, b);
  else if (b < WT_BLOCKS + VT_BLOCKS) vt_body(feat, b - WT_BLOCKS);
  else hp_body(cls_w, reg_w, b - WT_BLOCKS - VT_BLOCKS);
}

// ---------------- K1: winograd GEMM ----------------
__global__ __launch_bounds__(128) void wino_gemm_kernel() {
  __shared__ __align__(16) float As[2][KC3][64];
  __shared__ __align__(16) float Bs[2][KC3][128];

  const int mt = blockIdx.x;
  const int nt = blockIdx.y;
  const int z = blockIdx.z;
  const int xi = z >> 2;
  const int ks = z & 3;
  const int tid = threadIdx.x;
  const int warp = tid >> 5;
  const int lane = tid & 31;
  const int rg = lane >> 2;
  const int cg = lane & 3;
  const int am_off = rg * 8;
  const int bn_off = warp * 32 + cg * 8;

  const int am = tid & 63;
  const int akg = (tid >> 6) * 8;
  const int m = mt * 64 + am;
  const bool aval = (m < NTILE);
  const float* arow =
      g_Vt + (size_t)xi * VSTRIDE + (size_t)(aval ? m : 0) * CIN + ks * KPS + akg;

  const int bk = tid >> 3;
  const int bn = (tid & 7) * 16;
  const int n0 = nt * 128;
  const float* bsrc = g_Wt + (size_t)xi * KSTRIDE + (size_t)(ks * KPS + bk) * CMID + n0 + bn;

  float acc[8][8];
#pragma unroll
  for (int i = 0; i < 8; i++)
#pragma unroll
    for (int j = 0; j < 8; j++) acc[i][j] = 0.f;

  {
    float4 ra0 = aval ? *(const float4*)arow : make_float4(0.f, 0.f, 0.f, 0.f);
    float4 ra1 = aval ? *(const float4*)(arow + 4) : make_float4(0.f, 0.f, 0.f, 0.f);
#pragma unroll
    for (int i = 0; i < 4; i++) cp16(smem_u32(&Bs[0][bk][bn + i * 4]), bsrc + i * 4);
    CP_COMMIT();
    As[0][akg + 0][am] = ra0.x;
    As[0][akg + 1][am] = ra0.y;
    As[0][akg + 2][am] = ra0.z;
    As[0][akg + 3][am] = ra0.w;
    As[0][akg + 4][am] = ra1.x;
    As[0][akg + 5][am] = ra1.y;
    As[0][akg + 6][am] = ra1.z;
    As[0][akg + 7][am] = ra1.w;
    CP_WAIT0();
  }
  __syncthreads();

#pragma unroll 1
  for (int c = 0; c < CHKS; c++) {
    const int cur = c & 1;
    const int nxtb = cur ^ 1;
    float4 ra0, ra1;
    const bool more = (c + 1 < CHKS);
    if (more) {
      const int k0 = (c + 1) * KC3;
      ra0 = aval ? *(const float4*)(arow + k0) : make_float4(0.f, 0.f, 0.f, 0.f);
      ra1 = aval ? *(const float4*)(arow + k0 + 4) : make_float4(0.f, 0.f, 0.f, 0.f);
      const float* bs = bsrc + (size_t)k0 * CMID;
#pragma unroll
      for (int i = 0; i < 4; i++) cp16(smem_u32(&Bs[nxtb][bk][bn + i * 4]), bs + i * 4);
      CP_COMMIT();
    }
#pragma unroll
    for (int k = 0; k < KC3; k++) {
      float4 a0 = *(const float4*)&As[cur][k][am_off];
      float4 a1 = *(const float4*)&As[cur][k][am_off + 4];
      float4 b0 = *(const float4*)&Bs[cur][k][bn_off];
      float4 b1 = *(const float4*)&Bs[cur][k][bn_off + 4];
      float af[8] = {a0.x, a0.y, a0.z, a0.w, a1.x, a1.y, a1.z, a1.w};
      float bf[8] = {b0.x, b0.y, b0.z, b0.w, b1.x, b1.y, b1.z, b1.w};
#pragma unroll
      for (int i = 0; i < 8; i++)
#pragma unroll
        for (int j = 0; j < 8; j++) acc[i][j] = fmaf(af[i], bf[j], acc[i][j]);
    }
    if (more) {
      As[nxtb][akg + 0][am] = ra0.x;
      As[nxtb][akg + 1][am] = ra0.y;
      As[nxtb][akg + 2][am] = ra0.z;
      As[nxtb][akg + 3][am] = ra0.w;
      As[nxtb][akg + 4][am] = ra1.x;
      As[nxtb][akg + 5][am] = ra1.y;
      As[nxtb][akg + 6][am] = ra1.z;
      As[nxtb][akg + 7][am] = ra1.w;
      CP_WAIT0();
    }
    __syncthreads();
  }

  float* base = g_D + (size_t)z * DSTRIDE;
#pragma unroll
  for (int i = 0; i < 8; i++) {
    const int mr = mt * 64 + am_off + i;
    if (mr < NTILE) {  // skip padded-row stores
      float* dst = &base[(size_t)mr * CMID + n0 + bn_off];
      *(float4*)dst = make_float4(acc[i][0], acc[i][1], acc[i][2], acc[i][3]);
      *(float4*)(dst + 4) = make_float4(acc[i][4], acc[i][5], acc[i][6], acc[i][7]);
    }
  }
}

// ---------------- K2: inverse transform ----------------
__global__ __launch_bounds__(256) void inv_kernel(const float* __restrict__ bias) {
  const int tile = blockIdx.x;
  const int n = threadIdx.x;
  const int ty = tile / NT1D, tx = tile % NT1D;
  const size_t off = (size_t)tile * CMID + n;
  float M[6][6];
#pragma unroll
  for (int i = 0; i < 6; i++)
#pragma unroll
    for (int j = 0; j < 6; j++) {
      const int xi = i * 6 + j;
      M[i][j] = g_D[(size_t)(xi * 4 + 0) * DSTRIDE + off] +
                g_D[(size_t)(xi * 4 + 1) * DSTRIDE + off] +
                g_D[(size_t)(xi * 4 + 2) * DSTRIDE + off] +
                g_D[(size_t)(xi * 4 + 3) * DSTRIDE + off];
    }
  float S[4][6];
#pragma unroll
  for (int j = 0; j < 6; j++) {
    S[0][j] = M[0][j] + M[1][j] + M[2][j] + M[3][j] + M[4][j];
    S[1][j] = M[1][j] - M[2][j] + 2.f * M[3][j] - 2.f * M[4][j];
    S[2][j] = M[1][j] + M[2][j] + 4.f * M[3][j] + 4.f * M[4][j];
    S[3][j] = M[1][j] - M[2][j] + 8.f * M[3][j] - 8.f * M[4][j] + M[5][j];
  }
  const float b = bias[n];
#pragma unroll
  for (int a = 0; a < 4; a++) {
    float y0 = S[a][0] + S[a][1] + S[a][2] + S[a][3] + S[a][4] + b;
    float y1 = S[a][1] - S[a][2] + 2.f * S[a][3] - 2.f * S[a][4] + b;
    float y2 = S[a][1] + S[a][2] + 4.f * S[a][3] + 4.f * S[a][4] + b;
    float y3 = S[a][1] - S[a][2] + 8.f * S[a][3] - 8.f * S[a][4] + S[a][5] + b;
    const int py = 4 * ty + a;
    const int px = 4 * tx;
    g_x[(size_t)(py * WW + px + 0) * CMID + n] = fmaxf(y0, 0.f);
    g_x[(size_t)(py * WW + px + 1) * CMID + n] = fmaxf(y1, 0.f);
    g_x[(size_t)(py * WW + px + 2) * CMID + n] = fmaxf(y2, 0.f);
    g_x[(size_t)(py * WW + px + 3) * CMID + n] = fmaxf(y3, 0.f);
  }
}

// ---------------- K3: head mini-GEMM, 16 pixels/block, grid 100 ----------------
__global__ __launch_bounds__(256) void head_conv_kernel(
    const float* __restrict__ cls_b, const float* __restrict__ reg_b) {
  extern __shared__ float hs[];
  float* sx = hs;
  float* sw = hs + HOFF_SW;
  float* sout = hs + HOFF_SOUT;
  const int tid = threadIdx.x;
  const int p0 = blockIdx.x * 16;

  {
    const float4* s4 = (const float4*)(g_x + (size_t)p0 * CMID);
    float4* d4 = (float4*)sx;
    for (int i = tid; i < 16 * CMID / 4; i += 256) d4[i] = s4[i];
  }
  for (int i = tid; i < 30 * CMID; i += 256) {
    const int o = i >> 8, k = i & 255;
    sw[o * HSW_PITCH + k] = (o < 10) ? g_wcT[i] : g_wrT[i - 10 * CMID];
  }
  __syncthreads();

  // warp w -> pixels w*2, w*2+1 ; lane n -> output n
  const int warp = tid >> 5;
  const int n = tid & 31;
  float acc[2] = {0.f, 0.f};
  const float* wrow = sw + n * HSW_PITCH;
#pragma unroll 1
  for (int k0 = 0; k0 < CMID; k0 += 4) {
    const float w0 = wrow[k0], w1 = wrow[k0 + 1], w2 = wrow[k0 + 2], w3 = wrow[k0 + 3];
#pragma unroll
    for (int m = 0; m < 2; m++) {
      float4 xv = *(const float4*)&sx[(warp * 2 + m) * CMID + k0];
      acc[m] = fmaf(xv.x, w0, acc[m]);
      acc[m] = fmaf(xv.y, w1, acc[m]);
      acc[m] = fmaf(xv.z, w2, acc[m]);
      acc[m] = fmaf(xv.w, w3, acc[m]);
    }
  }
  if (n < 30) {
#pragma unroll
    for (int m = 0; m < 2; m++) sout[(warp * 2 + m) * 32 + n] = acc[m];
  }
  __syncthreads();

  for (int idx = tid; idx < 16 * NA; idx += 256) {
    const int lp = idx / NA, a = idx % NA;
    const float* so = sout + lp * 32;
    const int p = p0 + lp;
    float l0 = so[2 * a + 0] + cls_b[2 * a + 0];
    float l1 = so[2 * a + 1] + cls_b[2 * a + 1];
    float score = 1.f / (1.f + expf(l0 - l1));
    float d0 = so[10 + 4 * a + 0] + reg_b[4 * a + 0];
    float d1 = so[10 + 4 * a + 1] + reg_b[4 * a + 1];
    float d2 = so[10 + 4 * a + 2] + reg_b[4 * a + 2];
    float d3 = so[10 + 4 * a + 3] + reg_b[4 * a + 3];
    float base = 32.f * (float)(1 << a);
    float wdt = expf(d2) * base;
    float hgt = expf(d3) * base;
    float xc = (float)(p % WW) + d0;
    float yc = (float)(p / WW) + d1;
    const int bn = p * NA + a;
    g_scores[bn] = score;
    float4 b = make_float4(xc - 0.5f * wdt, yc - 0.5f * hgt,
                           xc + 0.5f * wdt, yc + 0.5f * hgt);
    *(float4*)&g_boxes[bn * 4] = b;
    g_rank[bn] = 0;
  }
}

// ---------------- K4a: counting rank ----------------
__global__ __launch_bounds__(256) void rank_kernel() {
  __shared__ unsigned long long skey[1000];
  const int i = blockIdx.x * 256 + threadIdx.x;
  const int j0 = blockIdx.y * 1000;
  for (int jj = threadIdx.x; jj < 1000; jj += 256) skey[jj] = score_key(j0 + jj);
  __syncthreads();
  if (i < NBOX) {
    const unsigned long long mykey = score_key(i);
    int cnt = 0;
#pragma unroll 4
    for (int jj = 0; jj < 1000; jj++) cnt += (int)(skey[jj] < mykey);
    if (cnt) atomicAdd(&g_rank[i], cnt);
  }
}

// ---------------- K4b: scatter ----------------
__global__ __launch_bounds__(256) void scatter_kernel() {
  const int i = blockIdx.x * 256 + threadIdx.x;
  if (i < NBOX) {
    const int r = g_rank[i];
    *(float4*)&g_boxsorted[r * 4] = *(const float4*)&g_boxes[i * 4];
  }
}

// ---------------- K4c: IoU masks ----------------
__global__ __launch_bounds__(64) void mask_kernel() {
  const int cb = blockIdx.x, rb = blockIdx.y;
  const int tid = threadIdx.x;
  const int i = rb * 64 + tid;
  if (cb < rb) {
    g_mask[(size_t)i * NWORD + cb] = 0ull;
    return;
  }
  __shared__ float cx1[64], cy1[64], cx2[64], cy2[64], car[64];
  {
    const int j = cb * 64 + tid;
    float4 b = *(const float4*)&g_boxsorted[j * 4];
    cx1[tid] = b.x; cy1[tid] = b.y; cx2[tid] = b.z; cy2[tid] = b.w;
    car[tid] = (b.z - b.x) * (b.w - b.y);
  }
  __syncthreads();
  float4 bi = *(const float4*)&g_boxsorted[i * 4];
  const float ia = (bi.z - bi.x) * (bi.w - bi.y);
  unsigned long long w = 0ull;
#pragma unroll 4
  for (int jj = 0; jj < 64; jj++) {
    const int j = cb * 64 + jj;
    float iw = fmaxf(fminf(bi.z, cx2[jj]) - fmaxf(bi.x, cx1[jj]), 0.f);
    float ih = fmaxf(fminf(bi.w, cy2[jj]) - fmaxf(bi.y, cy1[jj]), 0.f);
    float inter = iw * ih;
    float iou = inter / (ia + car[jj] - inter);
    if (j > i && iou >= 0.7f) w |= (1ull << jj);
  }
  g_mask[(size_t)i * NWORD + cb] = w;
}

// ---------------- K5: chunked greedy scan ----------------
__global__ __launch_bounds__(1024) void nms_scan_kernel() {
  extern __shared__ unsigned long long diag[];
  __shared__ unsigned long long remv[NWORD];
  __shared__ int ssel[MAXDET];
  __shared__ int keptl[64];
  const int tid = threadIdx.x;
  for (int j = tid; j < NBOX; j += 1024) diag[j] = g_mask[(size_t)j * NWORD + (j >> 6)];
  for (int w = tid; w < NWORD; w += 1024) remv[w] = 0ull;
  __syncthreads();
  if (tid >= 32) return;
  const int lane = tid;

  int count = 0;
#pragma unroll 1
  for (int c = 0; c < NWORD && count < MAXDET; c++) {
    int nk = 0;
    if (lane == 0) {
      unsigned long long avail = ~remv[c];
      while (avail && count < MAXDET) {
        const int b = __ffsll((long long)avail) - 1;
        const int j = (c << 6) + b;
        ssel[count++] = j;
        keptl[nk++] = j;
        avail &= ~(1ull << b);
        avail &= ~diag[j];
      }
    }
    nk = __shfl_sync(0xffffffffu, nk, 0);
    count = __shfl_sync(0xffffffffu, count, 0);
    __syncwarp();
    if (nk) {
      unsigned long long racc[4] = {0ull, 0ull, 0ull, 0ull};
      for (int q = 0; q < nk; q++) {
        const unsigned long long* row = g_mask + (size_t)keptl[q] * NWORD;
#pragma unroll
        for (int b2 = 0; b2 < 4; b2++) {
          const int w = lane + b2 * 32;
          if (w > c && w < NWORD) racc[b2] |= row[w];
        }
      }
#pragma unroll
      for (int b2 = 0; b2 < 4; b2++) {
        const int w = lane + b2 * 32;
        if (w > c && w < NWORD) remv[w] |= racc[b2];
      }
    }
    __syncwarp();
  }
  for (int r = lane; r < MAXDET; r += 32) {
    float4 v = make_float4(0.f, 0.f, 0.f, 0.f);
    if (r < count) v = *(const float4*)&g_boxsorted[ssel[r] * 4];
    *(float4*)&g_rois[r * 4] = v;
  }
}

// ---------------- K6: FC head ----------------
__global__ __launch_bounds__(128) void fc_head_kernel(
    const float* __restrict__ fc1_w, const float* __restrict__ fc1_b,
    const float* __restrict__ clsh_w, const float* __restrict__ clsh_b,
    const float* __restrict__ regh_w, const float* __restrict__ regh_b,
    float* __restrict__ out) {
  const int r = blockIdx.x;
  const int t = threadIdx.x;
  float4 roi = *(const float4*)&g_rois[r * 4];
  float part[8];
#pragma unroll
  for (int o = 0; o < 8; o++) part[o] = 0.f;
  for (int j = t; j < 1024; j += 128) {
    float f = fc1_b[j] + roi.x * fc1_w[j] + roi.y * fc1_w[1024 + j] +
              roi.z * fc1_w[2048 + j] + roi.w * fc1_w[3072 + j];
    f = fmaxf(f, 0.f);
    float4 cw = *(const float4*)&clsh_w[j * 4];
    float4 rw = *(const float4*)&regh_w[j * 4];
    part[0] += f * cw.x; part[1] += f * cw.y; part[2] += f * cw.z; part[3] += f * cw.w;
    part[4] += f * rw.x; part[5] += f * rw.y; part[6] += f * rw.z; part[7] += f * rw.w;
  }
#pragma unroll
  for (int o = 0; o < 8; o++) {
#pragma unroll
    for (int s = 16; s > 0; s >>= 1) part[o] += __shfl_xor_sync(0xffffffffu, part[o], s);
  }
  __shared__ float wred[4][8];
  const int warp = t >> 5, lane = t & 31;
  if (lane == 0) {
#pragma unroll
    for (int o = 0; o < 8; o++) wred[warp][o] = part[o];
  }
  __syncthreads();
  if (t == 0) {
    float v[8];
#pragma unroll
    for (int o = 0; o < 8; o++) v[o] = wred[0][o] + wred[1][o] + wred[2][o] + wred[3][o];
    float l0 = v[0] + clsh_b[0], l1 = v[1] + clsh_b[1];
    float l2 = v[2] + clsh_b[2], l3 = v[3] + clsh_b[3];
    float mx = fmaxf(fmaxf(l0, l1), fmaxf(l2, l3));
    float e0 = expf(l0 - mx), e1 = expf(l1 - mx), e2 = expf(l2 - mx), e3 = expf(l3 - mx);
    float inv = 1.f / (e0 + e1 + e2 + e3);
    out[r * 4 + 0] = e0 * inv;
    out[r * 4 + 1] = e1 * inv;
    out[r * 4 + 2] = e2 * inv;
    out[r * 4 + 3] = e3 * inv;
    out[1200 + r * 4 + 0] = v[4] + regh_b[0];
    out[1200 + r * 4 + 1] = v[5] + regh_b[1];
    out[1200 + r * 4 + 2] = v[6] + regh_b[2];
    out[1200 + r * 4 + 3] = v[7] + regh_b[3];
    *(float4*)&out[2400 + r * 4] = roi;
  }
}

// ---------------- launch ----------------
extern "C" void kernel_launch(void* const* d_in, const int* in_sizes, int n_in,
                              void* d_out, int out_size) {
  const float* feat   = (const float*)d_in[0];
  const float* conv_w = (const float*)d_in[1];
  const float* conv_b = (const float*)d_in[2];
  const float* cls_w  = (const float*)d_in[3];
  const float* cls_b  = (const float*)d_in[4];
  const float* reg_w  = (const float*)d_in[5];
  const float* reg_b  = (const float*)d_in[6];
  const float* fc1_w  = (const float*)d_in[7];
  const float* fc1_b  = (const float*)d_in[8];
  const float* clsh_w = (const float*)d_in[9];
  const float* clsh_b = (const float*)d_in[10];
  const float* regh_w = (const float*)d_in[11];
  const float* regh_b = (const float*)d_in[12];
  float* out = (float*)d_out;

  (void)in_sizes; (void)n_in; (void)out_size;

  cudaFuncSetAttribute(nms_scan_kernel, cudaFuncAttributeMaxDynamicSharedMemorySize,
                       NBOX * 8);
  cudaFuncSetAttribute(head_conv_kernel, cudaFuncAttributeMaxDynamicSharedMemorySize,
                       HSMEM_BYTES);

  transform_kernel<<<WT_BLOCKS + VT_BLOCKS + HP_BLOCKS, 256>>>(conv_w, feat, cls_w, reg_w);
  wino_gemm_kernel<<<dim3(2, 2, 144), 128>>>();
  inv_kernel<<<NTILE, 256>>>(conv_b);
  head_conv_kernel<<<100, 256, HSMEM_BYTES>>>(cls_b, reg_b);
  rank_kernel<<<dim3(32, 8), 256>>>();
  scatter_kernel<<<(NBOX + 255) / 256, 256>>>();
  mask_kernel<<<dim3(NWORD, NWORD), 64>>>();
  nms_scan_kernel<<<1, 1024, NBOX * 8>>>();
  fc_head_kernel<<<300, 128>>>(fc1_w, fc1_b, clsh_w, clsh_b, regh_w, regh_b, out);
}